// round 12
// baseline (speedup 1.0000x reference)
#include <cuda_runtime.h>
#include <cstdint>

#define NB 1024   // batch
#define NT 64     // time steps
#define ND 512    // input dim
#define NH 512    // hidden dim
#define NG 2048   // 4*H (gates)
#define NM 65536  // NB*NT rows of X / Z

#define KC     32           // K chunk per stage
#define SPAD   36           // smem row pitch in words (conflict-free; 36%32=4)
#define ZSTAGES 3           // zgemm pipeline depth
#define LSTAGES 4           // lstm pipeline depth (4th slot = cross-barrier B prefetch)

// ---------------- static device scratch (no allocations allowed) ----------
__device__ float g_Wt[NG * ND];        // W^T gate-interleaved, tf32 (4MB)
__device__ float g_Rt[NG * NH];        // R^T gate-interleaved, tf32 (4MB)
__device__ float g_Z[(size_t)NM * NG]; // Z = X@W + bias, interleaved cols (536MB)
__device__ float g_biasp[NG];          // permuted bias
__device__ float g_hbuf[2][NB * NH];   // double-buffered hidden state (tf32-rounded)
__device__ float g_cbuf[NB * NH];      // cell state
__device__ int   g_gbar[16];           // per-row-group step barrier counters

__device__ __forceinline__ uint32_t f2tf32(float f) {
    uint32_t r;
    asm("cvt.rna.tf32.f32 %0, %1;" : "=r"(r) : "f"(f));
    return r;
}
__device__ __forceinline__ void cpasync16(void* dst, const void* src) {
    uint32_t d = (uint32_t)__cvta_generic_to_shared(dst);
    asm volatile("cp.async.cg.shared.global [%0], [%1], 16;" :: "r"(d), "l"(src));
}
__device__ __forceinline__ void cp_commit() {
    asm volatile("cp.async.commit_group;");
}
__device__ __forceinline__ void cp_wait1() {
    asm volatile("cp.async.wait_group 1;");
}
// ldmatrix x4: each lane supplies the 16B row address of row (lane&7) of
// matrix (lane>>3). For 8x8-float tiles viewed as b16, lane gets element
// (lane>>2, lane&3) of its matrix -- identical to the tf32 mma fragment map.
__device__ __forceinline__ void ldsm_x4(uint32_t& r0, uint32_t& r1,
                                        uint32_t& r2, uint32_t& r3, uint32_t addr) {
    asm volatile("ldmatrix.sync.aligned.m8n8.x4.shared.b16 {%0,%1,%2,%3}, [%4];"
        : "=r"(r0), "=r"(r1), "=r"(r2), "=r"(r3) : "r"(addr));
}

__device__ __forceinline__ void mma_tf32(float* c, const uint32_t* a, const uint32_t* b) {
    asm volatile(
        "mma.sync.aligned.m16n8k8.row.col.f32.tf32.tf32.f32 "
        "{%0,%1,%2,%3}, {%4,%5,%6,%7}, {%8,%9}, {%0,%1,%2,%3};\n"
        : "+f"(c[0]), "+f"(c[1]), "+f"(c[2]), "+f"(c[3])
        : "r"(a[0]), "r"(a[1]), "r"(a[2]), "r"(a[3]),
          "r"(b[0]), "r"(b[1]));
}

__device__ __forceinline__ float sigmoidf_(float x) {
    return __fdividef(1.f, 1.f + __expf(-x));
}
__device__ __forceinline__ float tanhf_(float x) {
    return 2.f * sigmoidf_(2.f * x) - 1.f;
}

// ---------------- prep: permute/round weights, zero state -----------------
// Interleaved col n = h_idx*4 + gate  <->  original col j = gate*512 + h_idx.
__global__ void prep_kernel(const float* __restrict__ W,
                            const float* __restrict__ R,
                            const float* __restrict__ bias) {
    int tid = blockIdx.x * blockDim.x + threadIdx.x;
    int nthr = gridDim.x * blockDim.x;
    for (int i = tid; i < NG * ND; i += nthr) {
        int n = i >> 9;          // / 512
        int k = i & 511;
        int j = (n & 3) * NH + (n >> 2);
        g_Wt[i] = __uint_as_float(f2tf32(W[k * NG + j]));
        g_Rt[i] = __uint_as_float(f2tf32(R[k * NG + j]));
    }
    if (tid < NG) g_biasp[tid] = bias[(tid & 3) * NH + (tid >> 2)];
    if (tid < 16) g_gbar[tid] = 0;     // reset step barrier (fresh each replay)
    for (int i = tid; i < NB * NH; i += nthr) {
        g_hbuf[1][i] = 0.f;      // step 0 reads buffer 1
        g_cbuf[i] = 0.f;
    }
}

// ---------------- big parallel GEMM: Z = tf32(X) @ Wt^T + bias ------------
// M = 65536 (rows are (b,t)), N = 2048, K = 512. grid (16, 512), 128x128 tile.
#define ZSMEM (ZSTAGES * (128 + 128) * SPAD * 4)   // 110592

__device__ __forceinline__ void z_issue(uint32_t* sh, int slot, int kk, int tid,
                                        const float* __restrict__ x, int bm, int bn) {
    uint32_t* As = sh + slot * (128 + 128) * SPAD;
    uint32_t* Bs = As + 128 * SPAD;
    #pragma unroll
    for (int c = tid; c < 128 * 8; c += 256) {
        int row = c >> 3, q = (c & 7) << 2;
        cpasync16(As + row * SPAD + q, x + (size_t)(bm + row) * 512 + kk + q);
        cpasync16(Bs + row * SPAD + q, g_Wt + (size_t)(bn + row) * 512 + kk + q);
    }
}

__global__ __launch_bounds__(256, 2) void zgemm_kernel(const float* __restrict__ x) {
    extern __shared__ uint32_t sh[];
    const int tid = threadIdx.x;
    const int bm = blockIdx.y * 128;
    const int bn = blockIdx.x * 128;
    const int warp = tid >> 5, lane = tid & 31;
    const int wm = (warp >> 2) * 64, wn = (warp & 3) * 32;
    const int gid = lane >> 2, tg = lane & 3;

    float acc[4][4][4];
    #pragma unroll
    for (int i = 0; i < 4; i++)
        #pragma unroll
        for (int j = 0; j < 4; j++)
            #pragma unroll
            for (int r = 0; r < 4; r++) acc[i][j][r] = 0.f;

    z_issue(sh, 0, 0, tid, x, bm, bn); cp_commit();
    z_issue(sh, 1, KC, tid, x, bm, bn); cp_commit();

    const int NKT = ND / KC;   // 16
    for (int kt = 0; kt < NKT; kt++) {
        cp_wait1();
        __syncthreads();
        if (kt + 2 < NKT)
            z_issue(sh, (kt + 2) % ZSTAGES, (kt + 2) * KC, tid, x, bm, bn);
        cp_commit();
        // compute slot kt % ZSTAGES
        uint32_t* As = sh + (kt % ZSTAGES) * (128 + 128) * SPAD;
        uint32_t* Bs = As + 128 * SPAD;
        #pragma unroll
        for (int k8 = 0; k8 < KC; k8 += 8) {
            uint32_t a[4][4], b[4][2];
            #pragma unroll
            for (int mf = 0; mf < 4; mf++) {
                int rb = wm + mf * 16;
                a[mf][0] = f2tf32(__uint_as_float(As[(rb + gid) * SPAD + k8 + tg]));
                a[mf][1] = f2tf32(__uint_as_float(As[(rb + gid + 8) * SPAD + k8 + tg]));
                a[mf][2] = f2tf32(__uint_as_float(As[(rb + gid) * SPAD + k8 + tg + 4]));
                a[mf][3] = f2tf32(__uint_as_float(As[(rb + gid + 8) * SPAD + k8 + tg + 4]));
            }
            #pragma unroll
            for (int nf = 0; nf < 4; nf++) {
                int cb = wn + nf * 8;
                b[nf][0] = Bs[(cb + gid) * SPAD + k8 + tg];
                b[nf][1] = Bs[(cb + gid) * SPAD + k8 + tg + 4];
            }
            #pragma unroll
            for (int mf = 0; mf < 4; mf++)
                #pragma unroll
                for (int nf = 0; nf < 4; nf++)
                    mma_tf32(acc[mf][nf], a[mf], b[nf]);
        }
    }

    // store Z with bias folded in
    #pragma unroll
    for (int nf = 0; nf < 4; nf++) {
        int n0 = bn + wn + nf * 8 + 2 * tg;
        float2 bb = *(const float2*)(g_biasp + n0);
        #pragma unroll
        for (int mf = 0; mf < 4; mf++) {
            int r0 = bm + wm + mf * 16 + gid;
            *(float2*)(g_Z + (size_t)r0 * NG + n0) =
                make_float2(acc[mf][nf][0] + bb.x, acc[mf][nf][1] + bb.y);
            *(float2*)(g_Z + (size_t)(r0 + 8) * NG + n0) =
                make_float2(acc[mf][nf][2] + bb.x, acc[mf][nf][3] + bb.y);
        }
    }
}

// ---------------- persistent recurrence: all 64 steps in one kernel -------
// CTA tile 128(M) x 128(N), grid (16 bn, 8 bm) = 128 CTAs, 1/SM (210KB smem),
// 256 threads / 8 warps: 2M x 4N, warp tile 64x32 (MF=4). Fragments fed by
// ldmatrix.x4 (same element map as the scalar loads -> bit-identical math).
// cp.async pipeline: issue distance 2, wait1 => slot kt drained at iter kt.
#define LSTAGE_WORDS ((128 + 128) * SPAD)          // 9216
#define LZOFF (LSTAGES * LSTAGE_WORDS)             // Z region word offset
#define LZPITCH 132                                // Z smem row pitch (words)
#define LSMEM ((LZOFF + 128 * LZPITCH) * 4)        // 215040 bytes

__global__ __launch_bounds__(256, 1) void lstm_persist(float* __restrict__ out) {
    extern __shared__ uint32_t sh[];
    const uint32_t shb = (uint32_t)__cvta_generic_to_shared(sh);
    const int tid = threadIdx.x;
    const int grp = blockIdx.y;
    const int bm = blockIdx.y * 128;
    const int bn = blockIdx.x * 128;
    const int warp = tid >> 5, lane = tid & 31;
    const int wm = (warp >> 2) * 64, wn = (warp & 3) * 32;
    const int gid = lane >> 2, tg = lane & 3;
    const bool evn = (lane & 1) == 0;

    // ldmatrix per-lane row coordinates (words): matrix index = lane>>3
    const int arow = wm + (lane & 7) + ((lane >> 3) & 1) * 8;  // +mf*16 later
    const int acol = (lane >> 4) * 4;                          // +k8 later
    const int brow = wn + (lane & 7) + (lane >> 4) * 8;        // +p*16 later
    const int bcol = ((lane >> 3) & 1) * 4;                    // +k8 later

    // ---- cp.async helpers ----
    auto issueA = [&](int slot, int kk, const float* __restrict__ hsrc) {
        uint32_t* As = sh + slot * LSTAGE_WORDS;
        #pragma unroll
        for (int c = tid; c < 128 * 8; c += 256) {
            int row = c >> 3, q = (c & 7) << 2;
            cpasync16(As + row * SPAD + q, hsrc + (bm + row) * NH + kk + q);
        }
    };
    auto issueB = [&](int slot, int kk) {
        uint32_t* Bs = sh + slot * LSTAGE_WORDS + 128 * SPAD;
        #pragma unroll
        for (int c = tid; c < 128 * 8; c += 256) {
            int row = c >> 3, q = (c & 7) << 2;
            cpasync16(Bs + row * SPAD + q, g_Rt + (size_t)(bn + row) * NH + kk + q);
        }
    };
    auto issueZ = [&](int t) {
        uint32_t* Zs = sh + LZOFF;
        #pragma unroll
        for (int c = tid; c < 128 * 32; c += 256) {
            int row = c >> 5, q = (c & 31) << 2;
            cpasync16(Zs + row * LZPITCH + q,
                      g_Z + ((size_t)(bm + row) * NT + t) * NG + bn + q);
        }
    };

    // ---- prologue (t = 0 reads zeroed g_hbuf[1]) ----
    issueB(0, 0); issueB(1, KC); issueA(0, 0, g_hbuf[1]); cp_commit();
    issueA(1, KC, g_hbuf[1]); cp_commit();

    const int NKT = NH / KC;   // 16

    #pragma unroll 1
    for (int t = 0; t < NT; t++) {
        const float* __restrict__ hsrc = g_hbuf[(t + 1) & 1];
        float* __restrict__ hdst = g_hbuf[t & 1];

        float acc[4][4][4];
        #pragma unroll
        for (int i = 0; i < 4; i++)
            #pragma unroll
            for (int j = 0; j < 4; j++)
                #pragma unroll
                for (int r = 0; r < 4; r++) acc[i][j][r] = 0.f;

        #pragma unroll 1
        for (int kt = 0; kt < NKT; kt++) {
            cp_wait1();               // drains the group holding slot kt
            __syncthreads();
            if (kt <= NKT - 3) {
                int s = (kt + 2) & (LSTAGES - 1);
                issueA(s, (kt + 2) * KC, hsrc);
                issueB(s, (kt + 2) * KC);
                if (kt == NKT - 3) issueZ(t);       // drained by kt=15's wait
            } else if (t < NT - 1) {
                int s = kt - (NKT - 2);             // 0, 1: next-step B prefetch
                issueB(s, s * KC);
            }
            cp_commit();

            // compute slot kt % LSTAGES via ldmatrix.x4
            const uint32_t sbase = shb + ((kt & (LSTAGES - 1)) * LSTAGE_WORDS) * 4;
            const uint32_t bbase = sbase + (128 * SPAD) * 4;
            #pragma unroll
            for (int k8 = 0; k8 < KC; k8 += 8) {
                uint32_t a[4][4], bb[2][4];
                #pragma unroll
                for (int mf = 0; mf < 4; mf++)
                    ldsm_x4(a[mf][0], a[mf][1], a[mf][2], a[mf][3],
                            sbase + ((arow + mf * 16) * SPAD + k8 + acol) * 4);
                #pragma unroll
                for (int p = 0; p < 2; p++)
                    ldsm_x4(bb[p][0], bb[p][1], bb[p][2], bb[p][3],
                            bbase + ((brow + p * 16) * SPAD + k8 + bcol) * 4);
                #pragma unroll
                for (int mf = 0; mf < 4; mf++)
                    #pragma unroll
                    for (int nf = 0; nf < 4; nf++)
                        mma_tf32(acc[mf][nf], a[mf], &bb[nf >> 1][(nf & 1) * 2]);
            }
        }

        // ---- fused LSTM epilogue (Z + bias already in smem Z tile) ----
        const uint32_t* Zs = sh + LZOFF;
        #pragma unroll
        for (int nf = 0; nf < 4; nf++) {
            int nloc = wn + nf * 8 + 2 * tg;        // local col (even)
            int nblk = bn + wn + nf * 8;
            int hidx = (nblk >> 2) + (tg >> 1);
            #pragma unroll
            for (int mf = 0; mf < 4; mf++) {
                int rloc0 = wm + mf * 16 + gid;
                #pragma unroll
                for (int hh = 0; hh < 2; hh++) {
                    int rloc = rloc0 + hh * 8;
                    float2 zv = *(const float2*)(Zs + rloc * LZPITCH + nloc);
                    float v0 = acc[mf][nf][hh * 2 + 0] + zv.x;
                    float v1 = acc[mf][nf][hh * 2 + 1] + zv.y;
                    float p0 = __shfl_xor_sync(0xffffffffu, v0, 1);
                    float p1 = __shfl_xor_sync(0xffffffffu, v1, 1);
                    if (evn) {
                        float iv = sigmoidf_(v0);
                        float fv = sigmoidf_(v1);
                        float gv = tanhf_(p0);
                        float ov = sigmoidf_(p1);
                        int brow2 = bm + rloc;
                        int ci = brow2 * NH + hidx;
                        float cn = fv * g_cbuf[ci] + iv * gv;
                        float hn = ov * tanhf_(cn);
                        g_cbuf[ci] = cn;
                        hdst[ci] = __uint_as_float(f2tf32(hn));  // tf32 for next step
                        out[(size_t)brow2 * (NT * NH) + (size_t)t * NH + hidx] = hn;
                    }
                }
            }
        }

        // ---- per-group step barrier + next-step A refill ----
        if (t < NT - 1) {
            __threadfence();          // release h/c writes device-wide
            __syncthreads();          // all threads' writes + fences done
            if (tid == 0) {
                atomicAdd(&g_gbar[grp], 1);
                int target = 16 * (t + 1);          // monotonic, no reset race
                while (*(volatile int*)&g_gbar[grp] < target) { }
                __threadfence();      // acquire peers' h writes
            }
            __syncthreads();
            const float* __restrict__ hn = g_hbuf[t & 1];
            issueA(0, 0, hn); cp_commit();
            issueA(1, KC, hn); cp_commit();
        }
    }
}

extern "C" void kernel_launch(void* const* d_in, const int* in_sizes, int n_in,
                              void* d_out, int out_size) {
    const float* x    = (const float*)d_in[0]; // input_context [1024,64,512]
    const float* W    = (const float*)d_in[1]; // kernel [512,2048]
    const float* R    = (const float*)d_in[2]; // recurrent_kernel [512,2048]
    const float* bias = (const float*)d_in[3]; // bias [2048]
    float* out = (float*)d_out;                // [1024,64,512]

    cudaFuncSetAttribute(zgemm_kernel, cudaFuncAttributeMaxDynamicSharedMemorySize, ZSMEM);
    cudaFuncSetAttribute(lstm_persist, cudaFuncAttributeMaxDynamicSharedMemorySize, LSMEM);

    prep_kernel<<<512, 256>>>(W, R, bias);
    zgemm_kernel<<<dim3(16, 512), 256, ZSMEM>>>(x);
    lstm_persist<<<dim3(16, 8), 256, LSMEM>>>(out);
}